// round 3
// baseline (speedup 1.0000x reference)
#include <cuda_runtime.h>

// ---------------------------------------------------------------------------
// MeshUpConv: 3x spline_conv (kernel_size 3x3, degree 2 open B-spline)
//   L1: x[N,64]  -(W1,root1,b1)-> relu -> concat with skip -> h[N,64]
//   L2: h[N,64]  -(W1,root1,b1)-> relu -> h2[N,32]
//   L3: h2[N,32] -(W2,root2,b2)-> relu -> out[N,32]
// Edge message: msg_e = sum_k B[e,k] * (x[src_e] @ W[k]);  agg = scatter-add(dst)
// NOTE: edge_index arrives as int32 (JAX x64 disabled downcasts int64).
// ---------------------------------------------------------------------------

#define NMAX 50000
#define EMAX 400000

__device__ float g_acc[NMAX * 32];
__device__ float g_h[NMAX * 64];
__device__ float g_h2[NMAX * 32];

// ---- packed f32x2 helpers (sm_103a) ---------------------------------------
__device__ __forceinline__ unsigned long long pack2(float x) {
    unsigned long long r;
    asm("mov.b64 %0, {%1,%1};" : "=l"(r) : "f"(x));
    return r;
}
__device__ __forceinline__ void fma2(unsigned long long& d,
                                     unsigned long long a,
                                     unsigned long long b) {
    asm("fma.rn.f32x2 %0, %1, %2, %0;" : "+l"(d) : "l"(a), "l"(b));
}
__device__ __forceinline__ float2 unpack2(unsigned long long v) {
    float2 f;
    asm("mov.b64 {%0,%1}, %2;" : "=f"(f.x), "=f"(f.y) : "l"(v));
    return f;
}

// vectorized global reduction (sm_90+): 4 floats per REDG
__device__ __forceinline__ void red_add_v4(float* addr, float a, float b,
                                           float c, float d) {
    asm volatile("red.global.add.v4.f32 [%0], {%1,%2,%3,%4};"
                 :: "l"(addr), "f"(a), "f"(b), "f"(c), "f"(d)
                 : "memory");
}

// ---- node term: acc[n,o] = bias[o] + sum_c X[n,c]*root[c,o] ----------------
template <int CIN>
__global__ void __launch_bounds__(256) init_kernel(
    const float* __restrict__ X, const float* __restrict__ root,
    const float* __restrict__ bias, float* __restrict__ acc, int Nn) {
    __shared__ float rsm[CIN * 32];
    __shared__ float bsm[32];
    for (int i = threadIdx.x; i < CIN * 32; i += blockDim.x) rsm[i] = root[i];
    if (threadIdx.x < 32) bsm[threadIdx.x] = bias[threadIdx.x];
    __syncthreads();
    int n = (blockIdx.x * blockDim.x + threadIdx.x) >> 5;  // warp per node
    int o = threadIdx.x & 31;                              // lane = out channel
    if (n >= Nn) return;
    const float* xr = X + (long long)n * CIN;
    float s = bsm[o];
#pragma unroll
    for (int c = 0; c < CIN; c++) s += xr[c] * rsm[c * 32 + o];
    acc[n * 32 + o] = s;
}

// ---- edge kernel: thread per edge, W in smem (broadcast LDS), f32x2 FMA ----
template <int CIN>
__global__ void __launch_bounds__(256, 2) edge_kernel(
    const float* __restrict__ X, const int* __restrict__ ei,
    const float* __restrict__ pseudo, const float* __restrict__ W,
    float* __restrict__ acc, int E) {
    extern __shared__ unsigned long long Wsm2[];  // W as packed pairs
    float* Wsm = reinterpret_cast<float*>(Wsm2);
    const int WTOT = 9 * CIN * 32;
    for (int i = threadIdx.x; i < WTOT; i += 256) Wsm[i] = W[i];
    __syncthreads();

    int e = blockIdx.x * 256 + threadIdx.x;
    if (e >= E) return;

    int s = ei[e];      // src row of [2,E] int32
    int d = ei[E + e];  // dst row

    // open quadratic B-spline basis (kernel_size=3, degree=2): t in [0,1)
    float t0 = pseudo[2 * e], t1 = pseudo[2 * e + 1];
    float q0[3], q1[3];
    q0[0] = 0.5f * (1.f - t0) * (1.f - t0);
    q0[1] = -t0 * t0 + t0 + 0.5f;
    q0[2] = 0.5f * t0 * t0;
    q1[0] = 0.5f * (1.f - t1) * (1.f - t1);
    q1[1] = -t1 * t1 + t1 + 0.5f;
    q1[2] = 0.5f * t1 * t1;

    // gather source features into registers
    float xj[CIN];
    const float4* xr = reinterpret_cast<const float4*>(X + (long long)s * CIN);
#pragma unroll
    for (int i = 0; i < CIN / 4; i++) {
        float4 v = __ldg(xr + i);
        xj[4 * i + 0] = v.x;
        xj[4 * i + 1] = v.y;
        xj[4 * i + 2] = v.z;
        xj[4 * i + 3] = v.w;
    }

    // msg[32] as 16 packed f32x2 accumulators
    unsigned long long mm[16];
#pragma unroll
    for (int i = 0; i < 16; i++) mm[i] = 0ULL;

#pragma unroll
    for (int k1 = 0; k1 < 3; k1++) {
#pragma unroll
        for (int k0 = 0; k0 < 3; k0++) {
            float bk = q1[k1] * q0[k0];  // B[e, 3*k1 + k0]
            const unsigned long long* wk = Wsm2 + (k1 * 3 + k0) * CIN * 16;
#pragma unroll 2
            for (int c = 0; c < CIN; c++) {
                unsigned long long pp = pack2(bk * xj[c]);
                const ulonglong2* wc =
                    reinterpret_cast<const ulonglong2*>(wk + c * 16);
#pragma unroll
                for (int jj = 0; jj < 8; jj++) {
                    ulonglong2 w = wc[jj];  // LDS.128 broadcast
                    fma2(mm[2 * jj + 0], w.x, pp);
                    fma2(mm[2 * jj + 1], w.y, pp);
                }
            }
        }
    }

    float* dp = acc + (long long)d * 32;
#pragma unroll
    for (int j = 0; j < 8; j++) {
        float2 f0 = unpack2(mm[2 * j + 0]);
        float2 f1 = unpack2(mm[2 * j + 1]);
        red_add_v4(dp + 4 * j, f0.x, f0.y, f1.x, f1.y);
    }
}

// ---- epilogues -------------------------------------------------------------
__global__ void build_h_kernel(const float* __restrict__ acc,
                               const float* __restrict__ skip,
                               float* __restrict__ h, int Nn) {
    int i = blockIdx.x * blockDim.x + threadIdx.x;
    if (i >= Nn * 64) return;
    int n = i >> 6, c = i & 63;
    h[i] = (c < 32) ? fmaxf(acc[n * 32 + c], 0.f) : skip[n * 32 + (c - 32)];
}

__global__ void relu_copy_kernel(const float* __restrict__ acc,
                                 float* __restrict__ out, int total) {
    int i = blockIdx.x * blockDim.x + threadIdx.x;
    if (i < total) out[i] = fmaxf(acc[i], 0.f);
}

__global__ void relu_inplace_kernel(float* __restrict__ a, int total) {
    int i = blockIdx.x * blockDim.x + threadIdx.x;
    if (i < total) a[i] = fmaxf(a[i], 0.f);
}

// ---------------------------------------------------------------------------
extern "C" void kernel_launch(void* const* d_in, const int* in_sizes, int n_in,
                              void* d_out, int out_size) {
    const float* x = (const float*)d_in[0];      // [N,64]
    const int* ei = (const int*)d_in[1];         // [2,E] int32
    const float* pseudo = (const float*)d_in[2]; // [E,2]
    const float* skip = (const float*)d_in[3];   // [N,32]
    const float* W1 = (const float*)d_in[4];     // [9,64,32]
    const float* root1 = (const float*)d_in[5];  // [64,32]
    const float* b1 = (const float*)d_in[6];     // [32]
    const float* W2 = (const float*)d_in[7];     // [9,32,32]
    const float* root2 = (const float*)d_in[8];  // [32,32]
    const float* b2 = (const float*)d_in[9];     // [32]

    int Nn = in_sizes[0] / 64;
    int E = in_sizes[1] / 2;

    float *acc, *h, *h2;
    cudaGetSymbolAddress((void**)&acc, g_acc);
    cudaGetSymbolAddress((void**)&h, g_h);
    cudaGetSymbolAddress((void**)&h2, g_h2);

    const int SM64 = 9 * 64 * 32 * 4;  // 73728 B
    const int SM32 = 9 * 32 * 32 * 4;  // 36864 B
    cudaFuncSetAttribute(edge_kernel<64>,
                         cudaFuncAttributeMaxDynamicSharedMemorySize, SM64);
    cudaFuncSetAttribute(edge_kernel<32>,
                         cudaFuncAttributeMaxDynamicSharedMemorySize, SM32);

    int eb = (E + 255) / 256;
    int nb32 = (Nn * 32 + 255) / 256;
    int nb64 = (Nn * 64 + 255) / 256;
    float* out = (float*)d_out;

    // ---- layer 1: x -> acc ; h = [relu(acc), skip]
    init_kernel<64><<<nb32, 256>>>(x, root1, b1, acc, Nn);
    edge_kernel<64><<<eb, 256, SM64>>>(x, ei, pseudo, W1, acc, E);
    build_h_kernel<<<nb64, 256>>>(acc, skip, h, Nn);

    // ---- layer 2: h -> acc ; h2 = relu(acc)
    init_kernel<64><<<nb32, 256>>>(h, root1, b1, acc, Nn);
    edge_kernel<64><<<eb, 256, SM64>>>(h, ei, pseudo, W1, acc, E);
    relu_copy_kernel<<<nb32, 256>>>(acc, h2, Nn * 32);

    // ---- layer 3: h2 -> out ; out = relu(out)
    init_kernel<32><<<nb32, 256>>>(h2, root2, b2, out, Nn);
    edge_kernel<32><<<eb, 256, SM32>>>(h2, ei, pseudo, W2, out, E);
    relu_inplace_kernel<<<nb32, 256>>>(out, Nn * 32);
}

// round 4
// speedup vs baseline: 2.7560x; 2.7560x over previous
#include <cuda_runtime.h>

// ---------------------------------------------------------------------------
// MeshUpConv via node-domain weight transform:
//   Z[n, k*32+o] = (X @ W[k])[n,o]   (node GEMM, 10th slot = root -> acc+bias)
//   edge: acc[dst, o] += sum_k B[e,k] * Z[src, k*32+o]   (9 FMA/lane, 1 REDG)
// edge_index arrives as int32 (JAX x64 disabled).
// ---------------------------------------------------------------------------

#define NMAX 50000
#define EMAX 400000

__device__ float g_Z[NMAX * 288];   // 57.6 MB, k-slot features
__device__ float g_acc[NMAX * 32];
__device__ float g_h[NMAX * 64];
__device__ float g_h2[NMAX * 32];

// ---- packed f32x2 helpers (sm_103a) ---------------------------------------
__device__ __forceinline__ unsigned long long pack2(float x) {
    unsigned long long r;
    asm("mov.b64 %0, {%1,%1};" : "=l"(r) : "f"(x));
    return r;
}
__device__ __forceinline__ void fma2(unsigned long long& d,
                                     unsigned long long a,
                                     unsigned long long b) {
    asm("fma.rn.f32x2 %0, %1, %2, %0;" : "+l"(d) : "l"(a), "l"(b));
}
__device__ __forceinline__ float2 unpack2(unsigned long long v) {
    float2 f;
    asm("mov.b64 {%0,%1}, %2;" : "=f"(f.x), "=f"(f.y) : "l"(v));
    return f;
}
__device__ __forceinline__ void red_add_f32(float* addr, float v) {
    asm volatile("red.global.add.f32 [%0], %1;" :: "l"(addr), "f"(v) : "memory");
}

// ---- node GEMM: Z[n,0..287] = X@[W0..W8]; acc[n,:] = bias + X@root --------
// warp per node (grid-stride). Lane owns 5 column-pairs across the 10 slots.
template <int CIN>
__global__ void __launch_bounds__(256) node_gemm(
    const float* __restrict__ X, const float* __restrict__ W,
    const float* __restrict__ root, const float* __restrict__ bias,
    float* __restrict__ Z, float* __restrict__ acc, int Nn, int nwarps) {
    extern __shared__ float Wsm[];  // [10][CIN][32]: slots 0-8 = W, slot 9 = root
    __shared__ float bsm[32];
    const int WT = 9 * CIN * 32;
    for (int i = threadIdx.x; i < WT; i += 256) Wsm[i] = W[i];
    for (int i = threadIdx.x; i < CIN * 32; i += 256) Wsm[WT + i] = root[i];
    if (threadIdx.x < 32) bsm[threadIdx.x] = bias[threadIdx.x];
    __syncthreads();

    const unsigned long long* Wsm2 =
        reinterpret_cast<const unsigned long long*>(Wsm);
    int lane = threadIdx.x & 31;
    int gw = (blockIdx.x * 256 + threadIdx.x) >> 5;

    for (int n = gw; n < Nn; n += nwarps) {
        float xlo = X[n * CIN + lane];
        float xhi = (CIN == 64) ? X[n * CIN + 32 + lane] : 0.f;

        unsigned long long au[5];
#pragma unroll
        for (int i = 0; i < 5; i++) au[i] = 0ULL;

#pragma unroll
        for (int c = 0; c < CIN; c++) {
            float xc = __shfl_sync(0xffffffffu, (c < 32) ? xlo : xhi, c & 31);
            unsigned long long xp = pack2(xc);
#pragma unroll
            for (int i = 0; i < 5; i++) {
                int P = lane + 32 * i;  // global pair id 0..159
                fma2(au[i], Wsm2[(P >> 4) * (CIN * 16) + c * 16 + (P & 15)], xp);
            }
        }
#pragma unroll
        for (int i = 0; i < 5; i++) {
            int P = lane + 32 * i;
            int slot = P >> 4, pr = P & 15;
            float2 f = unpack2(au[i]);
            if (slot < 9) {
                *reinterpret_cast<float2*>(&Z[n * 288 + slot * 32 + 2 * pr]) = f;
            } else {
                acc[n * 32 + 2 * pr + 0] = f.x + bsm[2 * pr + 0];
                acc[n * 32 + 2 * pr + 1] = f.y + bsm[2 * pr + 1];
            }
        }
    }
}

// ---- edge phase: warp per edge, lane = output channel ----------------------
__global__ void __launch_bounds__(256) edge_kernel(
    const float* __restrict__ Z, const int* __restrict__ ei,
    const float* __restrict__ pseudo, float* __restrict__ acc, int E) {
    int gw = (blockIdx.x * 256 + threadIdx.x) >> 5;
    if (gw >= E) return;
    int lane = threadIdx.x & 31;

    int s = __ldg(ei + gw);
    int d = __ldg(ei + E + gw);
    float t0 = __ldg(pseudo + 2 * gw);
    float t1 = __ldg(pseudo + 2 * gw + 1);

    float q0[3], q1[3];
    q0[0] = 0.5f * (1.f - t0) * (1.f - t0);
    q0[1] = -t0 * t0 + t0 + 0.5f;
    q0[2] = 0.5f * t0 * t0;
    q1[0] = 0.5f * (1.f - t1) * (1.f - t1);
    q1[1] = -t1 * t1 + t1 + 0.5f;
    q1[2] = 0.5f * t1 * t1;

    const float* zs = Z + (long long)s * 288 + lane;
    float a = 0.f;
#pragma unroll
    for (int k1 = 0; k1 < 3; k1++)
#pragma unroll
        for (int k0 = 0; k0 < 3; k0++)
            a = fmaf(q1[k1] * q0[k0], __ldg(zs + (k1 * 3 + k0) * 32), a);

    red_add_f32(acc + (long long)d * 32 + lane, a);
}

// ---- epilogues -------------------------------------------------------------
__global__ void build_h_kernel(const float* __restrict__ acc,
                               const float* __restrict__ skip,
                               float* __restrict__ h, int Nn) {
    int i = blockIdx.x * blockDim.x + threadIdx.x;
    if (i >= Nn * 64) return;
    int n = i >> 6, c = i & 63;
    h[i] = (c < 32) ? fmaxf(acc[n * 32 + c], 0.f) : skip[n * 32 + (c - 32)];
}

__global__ void relu_copy_kernel(const float* __restrict__ acc,
                                 float* __restrict__ out, int total) {
    int i = blockIdx.x * blockDim.x + threadIdx.x;
    if (i < total) out[i] = fmaxf(acc[i], 0.f);
}

__global__ void relu_inplace_kernel(float* __restrict__ a, int total) {
    int i = blockIdx.x * blockDim.x + threadIdx.x;
    if (i < total) a[i] = fmaxf(a[i], 0.f);
}

// ---------------------------------------------------------------------------
extern "C" void kernel_launch(void* const* d_in, const int* in_sizes, int n_in,
                              void* d_out, int out_size) {
    const float* x = (const float*)d_in[0];      // [N,64]
    const int* ei = (const int*)d_in[1];         // [2,E] int32
    const float* pseudo = (const float*)d_in[2]; // [E,2]
    const float* skip = (const float*)d_in[3];   // [N,32]
    const float* W1 = (const float*)d_in[4];     // [9,64,32]
    const float* root1 = (const float*)d_in[5];  // [64,32]
    const float* b1 = (const float*)d_in[6];     // [32]
    const float* W2 = (const float*)d_in[7];     // [9,32,32]
    const float* root2 = (const float*)d_in[8];  // [32,32]
    const float* b2 = (const float*)d_in[9];     // [32]

    int Nn = in_sizes[0] / 64;
    int E = in_sizes[1] / 2;

    float *Z, *acc, *h, *h2;
    cudaGetSymbolAddress((void**)&Z, g_Z);
    cudaGetSymbolAddress((void**)&acc, g_acc);
    cudaGetSymbolAddress((void**)&h, g_h);
    cudaGetSymbolAddress((void**)&h2, g_h2);

    const int SM64 = 10 * 64 * 32 * 4;  // 81920 B
    const int SM32 = 10 * 32 * 32 * 4;  // 40960 B
    cudaFuncSetAttribute(node_gemm<64>,
                         cudaFuncAttributeMaxDynamicSharedMemorySize, SM64);
    cudaFuncSetAttribute(node_gemm<32>,
                         cudaFuncAttributeMaxDynamicSharedMemorySize, SM32);

    const int G64 = 296;   // 2 blocks/SM at 80KB smem
    const int G32 = 592;
    int eb = (E + 7) / 8;          // warp per edge, 8 edges/block
    int nb32 = (Nn * 32 + 255) / 256;
    int nb64 = (Nn * 64 + 255) / 256;
    float* out = (float*)d_out;

    // ---- layer 1: x -> acc ; h = [relu(acc), skip]
    node_gemm<64><<<G64, 256, SM64>>>(x, W1, root1, b1, Z, acc, Nn, G64 * 8);
    edge_kernel<<<eb, 256>>>(Z, ei, pseudo, acc, E);
    build_h_kernel<<<nb64, 256>>>(acc, skip, h, Nn);

    // ---- layer 2: h -> acc ; h2 = relu(acc)
    node_gemm<64><<<G64, 256, SM64>>>(h, W1, root1, b1, Z, acc, Nn, G64 * 8);
    edge_kernel<<<eb, 256>>>(Z, ei, pseudo, acc, E);
    relu_copy_kernel<<<nb32, 256>>>(acc, h2, Nn * 32);

    // ---- layer 3: h2 -> out
    node_gemm<32><<<G32, 256, SM32>>>(h2, W2, root2, b2, Z, out, Nn, G32 * 8);
    edge_kernel<<<eb, 256>>>(Z, ei, pseudo, out, E);
    relu_inplace_kernel<<<nb32, 256>>>(out, Nn * 32);
}

// round 5
// speedup vs baseline: 3.2200x; 1.1684x over previous
#include <cuda_runtime.h>

// ---------------------------------------------------------------------------
// MeshUpConv via node-domain weight transform, node-tiled GEMM (NT=4):
//   Z[n, k*32+o] = (X @ W[k])[n,o]; slot 9 = root -> acc (+bias)
//   edge: acc[dst, o] += sum_k B[e,k] * Z[src, k*32+o]
// Epilogues (relu / concat-with-skip) folded into the next layer's GEMM load.
// edge_index arrives as int32 (JAX x64 disabled).
// ---------------------------------------------------------------------------

#define NMAX 50000
#define EMAX 400000

__device__ float g_Z[NMAX * 288];
__device__ float g_acc1[NMAX * 32];
__device__ float g_acc2[NMAX * 32];

// ---- packed f32x2 helpers (sm_103a) ---------------------------------------
__device__ __forceinline__ unsigned long long pack2(float x) {
    unsigned long long r;
    asm("mov.b64 %0, {%1,%1};" : "=l"(r) : "f"(x));
    return r;
}
__device__ __forceinline__ void fma2(unsigned long long& d,
                                     unsigned long long a,
                                     unsigned long long b) {
    asm("fma.rn.f32x2 %0, %1, %2, %0;" : "+l"(d) : "l"(a), "l"(b));
}
__device__ __forceinline__ float2 unpack2(unsigned long long v) {
    float2 f;
    asm("mov.b64 {%0,%1}, %2;" : "=f"(f.x), "=f"(f.y) : "l"(v));
    return f;
}
__device__ __forceinline__ void red_add_f32(float* addr, float v) {
    asm volatile("red.global.add.f32 [%0], %1;" :: "l"(addr), "f"(v) : "memory");
}

// ---- node GEMM, 4 nodes per warp ------------------------------------------
// MODE 0: X plain [N,CIN];  MODE 1: [relu(A)||S] (CIN=64);  MODE 2: relu(A) (CIN=32)
template <int CIN, int MODE>
__global__ void __launch_bounds__(256) node_gemm(
    const float* __restrict__ Xa, const float* __restrict__ Xb,
    const float* __restrict__ W, const float* __restrict__ root,
    const float* __restrict__ bias, float* __restrict__ Z,
    float* __restrict__ acc, int Nn, int nwarps) {
    extern __shared__ float Wsm[];  // [10][CIN][32]: 0-8 = W, 9 = root
    __shared__ float bsm[32];
    const int WT = 9 * CIN * 32;
    for (int i = threadIdx.x; i < WT; i += 256) Wsm[i] = W[i];
    for (int i = threadIdx.x; i < CIN * 32; i += 256) Wsm[WT + i] = root[i];
    if (threadIdx.x < 32) bsm[threadIdx.x] = bias[threadIdx.x];
    __syncthreads();

    const unsigned long long* Wsm2 =
        reinterpret_cast<const unsigned long long*>(Wsm);
    int lane = threadIdx.x & 31;
    int gw = (blockIdx.x * 256 + threadIdx.x) >> 5;

    for (int n0 = gw * 4; n0 < Nn; n0 += nwarps * 4) {
        float xlo[4], xhi[4];
#pragma unroll
        for (int j = 0; j < 4; j++) {
            int n = n0 + j;
            bool v = (n < Nn);
            if (MODE == 0) {
                xlo[j] = v ? Xa[(long long)n * CIN + lane] : 0.f;
                xhi[j] = (CIN == 64 && v) ? Xa[(long long)n * CIN + 32 + lane] : 0.f;
            } else if (MODE == 1) {
                xlo[j] = v ? fmaxf(Xa[n * 32 + lane], 0.f) : 0.f;
                xhi[j] = v ? Xb[n * 32 + lane] : 0.f;
            } else {
                xlo[j] = v ? fmaxf(Xa[n * 32 + lane], 0.f) : 0.f;
                xhi[j] = 0.f;
            }
        }

        unsigned long long au[4][5];
#pragma unroll
        for (int j = 0; j < 4; j++)
#pragma unroll
            for (int i = 0; i < 5; i++) au[j][i] = 0ULL;

#pragma unroll
        for (int c = 0; c < CIN; c++) {
            unsigned long long w[5];
#pragma unroll
            for (int i = 0; i < 5; i++) {
                int P = lane + 32 * i;  // pair id 0..159
                w[i] = Wsm2[(P >> 4) * (CIN * 16) + c * 16 + (P & 15)];
            }
#pragma unroll
            for (int j = 0; j < 4; j++) {
                float xc =
                    __shfl_sync(0xffffffffu, (c < 32) ? xlo[j] : xhi[j], c & 31);
                unsigned long long xp = pack2(xc);
#pragma unroll
                for (int i = 0; i < 5; i++) fma2(au[j][i], w[i], xp);
            }
        }

#pragma unroll
        for (int j = 0; j < 4; j++) {
            int n = n0 + j;
            if (n >= Nn) break;
#pragma unroll
            for (int i = 0; i < 5; i++) {
                int P = lane + 32 * i;
                int slot = P >> 4, pr = P & 15;
                float2 f = unpack2(au[j][i]);
                if (slot < 9) {
                    *reinterpret_cast<float2*>(
                        &Z[(long long)n * 288 + slot * 32 + 2 * pr]) = f;
                } else {
                    acc[n * 32 + 2 * pr + 0] = f.x + bsm[2 * pr + 0];
                    acc[n * 32 + 2 * pr + 1] = f.y + bsm[2 * pr + 1];
                }
            }
        }
    }
}

// ---- edge phase: warp per edge, lane = output channel ----------------------
__global__ void __launch_bounds__(256) edge_kernel(
    const float* __restrict__ Z, const int* __restrict__ ei,
    const float* __restrict__ pseudo, float* __restrict__ acc, int E) {
    int gw = (blockIdx.x * 256 + threadIdx.x) >> 5;
    if (gw >= E) return;
    int lane = threadIdx.x & 31;

    int s = __ldg(ei + gw);
    int d = __ldg(ei + E + gw);
    float t0 = __ldg(pseudo + 2 * gw);
    float t1 = __ldg(pseudo + 2 * gw + 1);

    float q0[3], q1[3];
    q0[0] = 0.5f * (1.f - t0) * (1.f - t0);
    q0[1] = -t0 * t0 + t0 + 0.5f;
    q0[2] = 0.5f * t0 * t0;
    q1[0] = 0.5f * (1.f - t1) * (1.f - t1);
    q1[1] = -t1 * t1 + t1 + 0.5f;
    q1[2] = 0.5f * t1 * t1;

    const float* zs = Z + (long long)s * 288 + lane;
    float a = 0.f;
#pragma unroll
    for (int k1 = 0; k1 < 3; k1++)
#pragma unroll
        for (int k0 = 0; k0 < 3; k0++)
            a = fmaf(q1[k1] * q0[k0], __ldg(zs + (k1 * 3 + k0) * 32), a);

    red_add_f32(acc + (long long)d * 32 + lane, a);
}

__global__ void relu_inplace_kernel(float* __restrict__ a, int total) {
    int i = blockIdx.x * blockDim.x + threadIdx.x;
    if (i < total) a[i] = fmaxf(a[i], 0.f);
}

// ---------------------------------------------------------------------------
extern "C" void kernel_launch(void* const* d_in, const int* in_sizes, int n_in,
                              void* d_out, int out_size) {
    const float* x = (const float*)d_in[0];      // [N,64]
    const int* ei = (const int*)d_in[1];         // [2,E] int32
    const float* pseudo = (const float*)d_in[2]; // [E,2]
    const float* skip = (const float*)d_in[3];   // [N,32]
    const float* W1 = (const float*)d_in[4];     // [9,64,32]
    const float* root1 = (const float*)d_in[5];  // [64,32]
    const float* b1 = (const float*)d_in[6];     // [32]
    const float* W2 = (const float*)d_in[7];     // [9,32,32]
    const float* root2 = (const float*)d_in[8];  // [32,32]
    const float* b2 = (const float*)d_in[9];     // [32]

    int Nn = in_sizes[0] / 64;
    int E = in_sizes[1] / 2;

    float *Z, *acc1, *acc2;
    cudaGetSymbolAddress((void**)&Z, g_Z);
    cudaGetSymbolAddress((void**)&acc1, g_acc1);
    cudaGetSymbolAddress((void**)&acc2, g_acc2);

    const int SM64 = 10 * 64 * 32 * 4;  // 81920 B
    const int SM32 = 10 * 32 * 32 * 4;  // 40960 B
    cudaFuncSetAttribute(node_gemm<64, 0>,
                         cudaFuncAttributeMaxDynamicSharedMemorySize, SM64);
    cudaFuncSetAttribute(node_gemm<64, 1>,
                         cudaFuncAttributeMaxDynamicSharedMemorySize, SM64);
    cudaFuncSetAttribute(node_gemm<32, 2>,
                         cudaFuncAttributeMaxDynamicSharedMemorySize, SM32);

    const int G64 = 296;   // 2 blocks/SM (80 KB smem each)
    const int G32 = 592;
    int eb = (E + 7) / 8;  // warp per edge
    int nb32 = (Nn * 32 + 255) / 256;
    float* out = (float*)d_out;

    // ---- layer 1: x -> Z, acc1(root) ; edge -> acc1
    node_gemm<64, 0><<<G64, 256, SM64>>>(x, nullptr, W1, root1, b1, Z, acc1,
                                         Nn, G64 * 8);
    edge_kernel<<<eb, 256>>>(Z, ei, pseudo, acc1, E);

    // ---- layer 2: [relu(acc1)||skip] -> Z, acc2(root) ; edge -> acc2
    node_gemm<64, 1><<<G64, 256, SM64>>>(acc1, skip, W1, root1, b1, Z, acc2,
                                         Nn, G64 * 8);
    edge_kernel<<<eb, 256>>>(Z, ei, pseudo, acc2, E);

    // ---- layer 3: relu(acc2) -> Z, out(root) ; edge -> out ; relu
    node_gemm<32, 2><<<G32, 256, SM32>>>(acc2, nullptr, W2, root2, b2, Z, out,
                                         Nn, G32 * 8);
    edge_kernel<<<eb, 256>>>(Z, ei, pseudo, out, E);
    relu_inplace_kernel<<<nb32, 256>>>(out, Nn * 32);
}

// round 6
// speedup vs baseline: 5.8851x; 1.8277x over previous
#include <cuda_runtime.h>

// ---------------------------------------------------------------------------
// MeshUpConv via node-domain weight transform, node-tiled GEMM (NT=4):
//   Z[n, k*32+o] = (X @ W[k])[n,o]; slot 9 = root -> acc (+bias)
//   edge: acc[dst, o] += sum_k B[e,k] * Z[src, k*32+o]
// Edge phase: 8 lanes/edge, float4 channels, vectorized REDG (v4).
// Epilogues (relu / concat-with-skip) folded into the next layer's GEMM load.
// edge_index arrives as int32 (JAX x64 disabled).
// ---------------------------------------------------------------------------

#define NMAX 50000
#define EMAX 400000

__device__ float g_Z[NMAX * 288];
__device__ float g_acc1[NMAX * 32];
__device__ float g_acc2[NMAX * 32];

// ---- packed f32x2 helpers (sm_103a) ---------------------------------------
__device__ __forceinline__ unsigned long long pack2(float x) {
    unsigned long long r;
    asm("mov.b64 %0, {%1,%1};" : "=l"(r) : "f"(x));
    return r;
}
__device__ __forceinline__ void fma2(unsigned long long& d,
                                     unsigned long long a,
                                     unsigned long long b) {
    asm("fma.rn.f32x2 %0, %1, %2, %0;" : "+l"(d) : "l"(a), "l"(b));
}
__device__ __forceinline__ float2 unpack2(unsigned long long v) {
    float2 f;
    asm("mov.b64 {%0,%1}, %2;" : "=f"(f.x), "=f"(f.y) : "l"(v));
    return f;
}
__device__ __forceinline__ void red_add_v4(float* addr, float a, float b,
                                           float c, float d) {
    asm volatile("red.global.add.v4.f32 [%0], {%1,%2,%3,%4};"
                 :: "l"(addr), "f"(a), "f"(b), "f"(c), "f"(d)
                 : "memory");
}

// ---- node GEMM, 4 nodes per warp ------------------------------------------
// MODE 0: X plain [N,CIN];  MODE 1: [relu(A)||S] (CIN=64);  MODE 2: relu(A) (CIN=32)
template <int CIN, int MODE>
__global__ void __launch_bounds__(256) node_gemm(
    const float* __restrict__ Xa, const float* __restrict__ Xb,
    const float* __restrict__ W, const float* __restrict__ root,
    const float* __restrict__ bias, float* __restrict__ Z,
    float* __restrict__ acc, int Nn, int nwarps) {
    extern __shared__ float Wsm[];  // [10][CIN][32]: 0-8 = W, 9 = root
    __shared__ float bsm[32];
    const int WT = 9 * CIN * 32;
    for (int i = threadIdx.x; i < WT; i += 256) Wsm[i] = W[i];
    for (int i = threadIdx.x; i < CIN * 32; i += 256) Wsm[WT + i] = root[i];
    if (threadIdx.x < 32) bsm[threadIdx.x] = bias[threadIdx.x];
    __syncthreads();

    const unsigned long long* Wsm2 =
        reinterpret_cast<const unsigned long long*>(Wsm);
    int lane = threadIdx.x & 31;
    int gw = (blockIdx.x * 256 + threadIdx.x) >> 5;

    for (int n0 = gw * 4; n0 < Nn; n0 += nwarps * 4) {
        float xlo[4], xhi[4];
#pragma unroll
        for (int j = 0; j < 4; j++) {
            int n = n0 + j;
            bool v = (n < Nn);
            if (MODE == 0) {
                xlo[j] = v ? Xa[(long long)n * CIN + lane] : 0.f;
                xhi[j] = (CIN == 64 && v) ? Xa[(long long)n * CIN + 32 + lane] : 0.f;
            } else if (MODE == 1) {
                xlo[j] = v ? fmaxf(Xa[n * 32 + lane], 0.f) : 0.f;
                xhi[j] = v ? Xb[n * 32 + lane] : 0.f;
            } else {
                xlo[j] = v ? fmaxf(Xa[n * 32 + lane], 0.f) : 0.f;
                xhi[j] = 0.f;
            }
        }

        unsigned long long au[4][5];
#pragma unroll
        for (int j = 0; j < 4; j++)
#pragma unroll
            for (int i = 0; i < 5; i++) au[j][i] = 0ULL;

#pragma unroll
        for (int c = 0; c < CIN; c++) {
            unsigned long long w[5];
#pragma unroll
            for (int i = 0; i < 5; i++) {
                int P = lane + 32 * i;  // pair id 0..159
                w[i] = Wsm2[(P >> 4) * (CIN * 16) + c * 16 + (P & 15)];
            }
#pragma unroll
            for (int j = 0; j < 4; j++) {
                float xc =
                    __shfl_sync(0xffffffffu, (c < 32) ? xlo[j] : xhi[j], c & 31);
                unsigned long long xp = pack2(xc);
#pragma unroll
                for (int i = 0; i < 5; i++) fma2(au[j][i], w[i], xp);
            }
        }

#pragma unroll
        for (int j = 0; j < 4; j++) {
            int n = n0 + j;
            if (n >= Nn) break;
#pragma unroll
            for (int i = 0; i < 5; i++) {
                int P = lane + 32 * i;
                int slot = P >> 4, pr = P & 15;
                float2 f = unpack2(au[j][i]);
                if (slot < 9) {
                    *reinterpret_cast<float2*>(
                        &Z[(long long)n * 288 + slot * 32 + 2 * pr]) = f;
                } else {
                    acc[n * 32 + 2 * pr + 0] = f.x + bsm[2 * pr + 0];
                    acc[n * 32 + 2 * pr + 1] = f.y + bsm[2 * pr + 1];
                }
            }
        }
    }
}

// ---- edge phase: 8 lanes per edge, float4 channels -------------------------
__global__ void __launch_bounds__(256) edge_kernel(
    const float* __restrict__ Z, const int* __restrict__ ei,
    const float* __restrict__ pseudo, float* __restrict__ acc, int E) {
    int warp = (blockIdx.x * 256 + threadIdx.x) >> 5;
    int lane = threadIdx.x & 31;
    int sub = lane >> 3;   // edge within warp (0..3)
    int li = lane & 7;     // float4-channel (0..7)
    int e = warp * 4 + sub;
    if (e >= E) return;

    int s = __ldg(ei + e);
    int d = __ldg(ei + E + e);
    float2 ps = __ldg(reinterpret_cast<const float2*>(pseudo) + e);
    float t0 = ps.x, t1 = ps.y;

    float q0[3], q1[3];
    q0[0] = 0.5f * (1.f - t0) * (1.f - t0);
    q0[1] = -t0 * t0 + t0 + 0.5f;
    q0[2] = 0.5f * t0 * t0;
    q1[0] = 0.5f * (1.f - t1) * (1.f - t1);
    q1[1] = -t1 * t1 + t1 + 0.5f;
    q1[2] = 0.5f * t1 * t1;

    const float4* zs =
        reinterpret_cast<const float4*>(Z + (long long)s * 288) + li;
    float4 a = make_float4(0.f, 0.f, 0.f, 0.f);
#pragma unroll
    for (int k1 = 0; k1 < 3; k1++) {
#pragma unroll
        for (int k0 = 0; k0 < 3; k0++) {
            float bk = q1[k1] * q0[k0];
            float4 z = __ldg(zs + (k1 * 3 + k0) * 8);
            a.x = fmaf(bk, z.x, a.x);
            a.y = fmaf(bk, z.y, a.y);
            a.z = fmaf(bk, z.z, a.z);
            a.w = fmaf(bk, z.w, a.w);
        }
    }

    red_add_v4(acc + (long long)d * 32 + li * 4, a.x, a.y, a.z, a.w);
}

__global__ void relu4_kernel(float4* __restrict__ a, int total4) {
    int i = blockIdx.x * blockDim.x + threadIdx.x;
    if (i < total4) {
        float4 v = a[i];
        v.x = fmaxf(v.x, 0.f); v.y = fmaxf(v.y, 0.f);
        v.z = fmaxf(v.z, 0.f); v.w = fmaxf(v.w, 0.f);
        a[i] = v;
    }
}

// ---------------------------------------------------------------------------
extern "C" void kernel_launch(void* const* d_in, const int* in_sizes, int n_in,
                              void* d_out, int out_size) {
    const float* x = (const float*)d_in[0];      // [N,64]
    const int* ei = (const int*)d_in[1];         // [2,E] int32
    const float* pseudo = (const float*)d_in[2]; // [E,2]
    const float* skip = (const float*)d_in[3];   // [N,32]
    const float* W1 = (const float*)d_in[4];     // [9,64,32]
    const float* root1 = (const float*)d_in[5];  // [64,32]
    const float* b1 = (const float*)d_in[6];     // [32]
    const float* W2 = (const float*)d_in[7];     // [9,32,32]
    const float* root2 = (const float*)d_in[8];  // [32,32]
    const float* b2 = (const float*)d_in[9];     // [32]

    int Nn = in_sizes[0] / 64;
    int E = in_sizes[1] / 2;

    float *Z, *acc1, *acc2;
    cudaGetSymbolAddress((void**)&Z, g_Z);
    cudaGetSymbolAddress((void**)&acc1, g_acc1);
    cudaGetSymbolAddress((void**)&acc2, g_acc2);

    const int SM64 = 10 * 64 * 32 * 4;  // 81920 B
    const int SM32 = 10 * 32 * 32 * 4;  // 40960 B
    cudaFuncSetAttribute(node_gemm<64, 0>,
                         cudaFuncAttributeMaxDynamicSharedMemorySize, SM64);
    cudaFuncSetAttribute(node_gemm<64, 1>,
                         cudaFuncAttributeMaxDynamicSharedMemorySize, SM64);
    cudaFuncSetAttribute(node_gemm<32, 2>,
                         cudaFuncAttributeMaxDynamicSharedMemorySize, SM32);

    const int G64 = 296;   // 2 blocks/SM (80 KB smem each)
    const int G32 = 592;
    int eb = (E + 31) / 32;  // 4 edges/warp, 8 warps/block
    int nb4 = (Nn * 32 / 4 + 255) / 256;
    float* out = (float*)d_out;

    // ---- layer 1: x -> Z, acc1(root) ; edge -> acc1
    node_gemm<64, 0><<<G64, 256, SM64>>>(x, nullptr, W1, root1, b1, Z, acc1,
                                         Nn, G64 * 8);
    edge_kernel<<<eb, 256>>>(Z, ei, pseudo, acc1, E);

    // ---- layer 2: [relu(acc1)||skip] -> Z, acc2(root) ; edge -> acc2
    node_gemm<64, 1><<<G64, 256, SM64>>>(acc1, skip, W1, root1, b1, Z, acc2,
                                         Nn, G64 * 8);
    edge_kernel<<<eb, 256>>>(Z, ei, pseudo, acc2, E);

    // ---- layer 3: relu(acc2) -> Z, out(root) ; edge -> out ; relu
    node_gemm<32, 2><<<G32, 256, SM32>>>(acc2, nullptr, W2, root2, b2, Z, out,
                                         Nn, G32 * 8);
    edge_kernel<<<eb, 256>>>(Z, ei, pseudo, out, E);
    relu4_kernel<<<nb4, 256>>>((float4*)out, Nn * 32 / 4);
}

// round 7
// speedup vs baseline: 6.6974x; 1.1380x over previous
#include <cuda_runtime.h>
#include <cuda_fp16.h>

// ---------------------------------------------------------------------------
// MeshUpConv via node-domain weight transform:
//   Z[n, k*32+o] = (X @ W[k])[n,o]  stored fp16 (gather traffic halved);
//   slot 9 = root -> acc (+bias), fp32.
//   edge: acc[dst, o] += sum_k B[e,k] * Z[src, k*32+o]   (fp32 accumulate)
// Node GEMM: 8 nodes/warp (W smem traffic amortized 8x), f32x2 FMA.
// Epilogues (relu / concat-with-skip) folded into next layer's GEMM load.
// edge_index arrives as int32 (JAX x64 disabled).
// ---------------------------------------------------------------------------

#define NMAX 50000
#define EMAX 400000

__device__ __half g_Zh[NMAX * 288];   // 28.8 MB, L2-resident
__device__ float g_acc1[NMAX * 32];
__device__ float g_acc2[NMAX * 32];

// ---- packed f32x2 helpers (sm_103a) ---------------------------------------
__device__ __forceinline__ unsigned long long pack2(float x) {
    unsigned long long r;
    asm("mov.b64 %0, {%1,%1};" : "=l"(r) : "f"(x));
    return r;
}
__device__ __forceinline__ void fma2(unsigned long long& d,
                                     unsigned long long a,
                                     unsigned long long b) {
    asm("fma.rn.f32x2 %0, %1, %2, %0;" : "+l"(d) : "l"(a), "l"(b));
}
__device__ __forceinline__ float2 unpack2(unsigned long long v) {
    float2 f;
    asm("mov.b64 {%0,%1}, %2;" : "=f"(f.x), "=f"(f.y) : "l"(v));
    return f;
}
__device__ __forceinline__ void red_add_v4(float* addr, float a, float b,
                                           float c, float d) {
    asm volatile("red.global.add.v4.f32 [%0], {%1,%2,%3,%4};"
                 :: "l"(addr), "f"(a), "f"(b), "f"(c), "f"(d)
                 : "memory");
}

// ---- node GEMM, 8 nodes per warp ------------------------------------------
// MODE 0: X plain [N,CIN];  MODE 1: [relu(A)||S] (CIN=64);  MODE 2: relu(A) (CIN=32)
template <int CIN, int MODE>
__global__ void __launch_bounds__(256, 2) node_gemm(
    const float* __restrict__ Xa, const float* __restrict__ Xb,
    const float* __restrict__ W, const float* __restrict__ root,
    const float* __restrict__ bias, __half* __restrict__ Zh,
    float* __restrict__ acc, int Nn, int nwarps) {
    extern __shared__ float Wsm[];  // [10][CIN][32]: 0-8 = W, 9 = root
    __shared__ float bsm[32];
    const int WT = 9 * CIN * 32;
    for (int i = threadIdx.x; i < WT; i += 256) Wsm[i] = W[i];
    for (int i = threadIdx.x; i < CIN * 32; i += 256) Wsm[WT + i] = root[i];
    if (threadIdx.x < 32) bsm[threadIdx.x] = bias[threadIdx.x];
    __syncthreads();

    const unsigned long long* Wsm2 =
        reinterpret_cast<const unsigned long long*>(Wsm);
    int lane = threadIdx.x & 31;
    int gw = (blockIdx.x * 256 + threadIdx.x) >> 5;

    for (int n0 = gw * 8; n0 < Nn; n0 += nwarps * 8) {
        float xlo[8], xhi[8];
#pragma unroll
        for (int j = 0; j < 8; j++) {
            int n = n0 + j;
            bool v = (n < Nn);
            if (MODE == 0) {
                xlo[j] = v ? Xa[(long long)n * CIN + lane] : 0.f;
                xhi[j] = (CIN == 64 && v) ? Xa[(long long)n * CIN + 32 + lane] : 0.f;
            } else if (MODE == 1) {
                xlo[j] = v ? fmaxf(Xa[n * 32 + lane], 0.f) : 0.f;
                xhi[j] = v ? Xb[n * 32 + lane] : 0.f;
            } else {
                xlo[j] = v ? fmaxf(Xa[n * 32 + lane], 0.f) : 0.f;
                xhi[j] = 0.f;
            }
        }

        unsigned long long au[8][5];
#pragma unroll
        for (int j = 0; j < 8; j++)
#pragma unroll
            for (int i = 0; i < 5; i++) au[j][i] = 0ULL;

#pragma unroll
        for (int c = 0; c < CIN; c++) {
            unsigned long long w[5];
#pragma unroll
            for (int i = 0; i < 5; i++) {
                int P = lane + 32 * i;  // pair id 0..159
                w[i] = Wsm2[(P >> 4) * (CIN * 16) + c * 16 + (P & 15)];
            }
#pragma unroll
            for (int j = 0; j < 8; j++) {
                float xc =
                    __shfl_sync(0xffffffffu, (c < 32) ? xlo[j] : xhi[j], c & 31);
                unsigned long long xp = pack2(xc);
#pragma unroll
                for (int i = 0; i < 5; i++) fma2(au[j][i], w[i], xp);
            }
        }

#pragma unroll
        for (int j = 0; j < 8; j++) {
            int n = n0 + j;
            if (n >= Nn) break;
#pragma unroll
            for (int i = 0; i < 5; i++) {
                int P = lane + 32 * i;
                int slot = P >> 4, pr = P & 15;
                float2 f = unpack2(au[j][i]);
                if (slot < 9) {
                    // half index 2P = slot*32 + 2*pr; coalesced half2 stores
                    *reinterpret_cast<__half2*>(&Zh[(long long)n * 288 + 2 * P]) =
                        __floats2half2_rn(f.x, f.y);
                } else {
                    acc[n * 32 + 2 * pr + 0] = f.x + bsm[2 * pr + 0];
                    acc[n * 32 + 2 * pr + 1] = f.y + bsm[2 * pr + 1];
                }
            }
        }
    }
}

// ---- edge phase: 8 lanes/edge, 4 fp16 channels per lane, fp32 accumulate ---
__global__ void __launch_bounds__(256) edge_kernel(
    const __half* __restrict__ Zh, const int* __restrict__ ei,
    const float* __restrict__ pseudo, float* __restrict__ acc, int E) {
    int warp = (blockIdx.x * 256 + threadIdx.x) >> 5;
    int lane = threadIdx.x & 31;
    int sub = lane >> 3;   // edge within warp (0..3)
    int li = lane & 7;     // half4-channel group (0..7)
    int e = warp * 4 + sub;
    if (e >= E) return;

    int s = __ldg(ei + e);
    int d = __ldg(ei + E + e);
    float2 ps = __ldg(reinterpret_cast<const float2*>(pseudo) + e);
    float t0 = ps.x, t1 = ps.y;

    float q0[3], q1[3];
    q0[0] = 0.5f * (1.f - t0) * (1.f - t0);
    q0[1] = -t0 * t0 + t0 + 0.5f;
    q0[2] = 0.5f * t0 * t0;
    q1[0] = 0.5f * (1.f - t1) * (1.f - t1);
    q1[1] = -t1 * t1 + t1 + 0.5f;
    q1[2] = 0.5f * t1 * t1;

    // lane reads 4 halves (8B) per slot at half-offset k*32 + li*4
    const uint2* zs =
        reinterpret_cast<const uint2*>(Zh + (long long)s * 288) + li;
    float ax = 0.f, ay = 0.f, az = 0.f, aw = 0.f;
#pragma unroll
    for (int k1 = 0; k1 < 3; k1++) {
#pragma unroll
        for (int k0 = 0; k0 < 3; k0++) {
            float bk = q1[k1] * q0[k0];
            uint2 z = __ldg(zs + (k1 * 3 + k0) * 8);
            float2 f0 = __half22float2(*reinterpret_cast<__half2*>(&z.x));
            float2 f1 = __half22float2(*reinterpret_cast<__half2*>(&z.y));
            ax = fmaf(bk, f0.x, ax);
            ay = fmaf(bk, f0.y, ay);
            az = fmaf(bk, f1.x, az);
            aw = fmaf(bk, f1.y, aw);
        }
    }

    red_add_v4(acc + (long long)d * 32 + li * 4, ax, ay, az, aw);
}

__global__ void relu4_kernel(float4* __restrict__ a, int total4) {
    int i = blockIdx.x * blockDim.x + threadIdx.x;
    if (i < total4) {
        float4 v = a[i];
        v.x = fmaxf(v.x, 0.f); v.y = fmaxf(v.y, 0.f);
        v.z = fmaxf(v.z, 0.f); v.w = fmaxf(v.w, 0.f);
        a[i] = v;
    }
}

// ---------------------------------------------------------------------------
extern "C" void kernel_launch(void* const* d_in, const int* in_sizes, int n_in,
                              void* d_out, int out_size) {
    const float* x = (const float*)d_in[0];      // [N,64]
    const int* ei = (const int*)d_in[1];         // [2,E] int32
    const float* pseudo = (const float*)d_in[2]; // [E,2]
    const float* skip = (const float*)d_in[3];   // [N,32]
    const float* W1 = (const float*)d_in[4];     // [9,64,32]
    const float* root1 = (const float*)d_in[5];  // [64,32]
    const float* b1 = (const float*)d_in[6];     // [32]
    const float* W2 = (const float*)d_in[7];     // [9,32,32]
    const float* root2 = (const float*)d_in[8];  // [32,32]
    const float* b2 = (const float*)d_in[9];     // [32]

    int Nn = in_sizes[0] / 64;
    int E = in_sizes[1] / 2;

    __half* Zh;
    float *acc1, *acc2;
    cudaGetSymbolAddress((void**)&Zh, g_Zh);
    cudaGetSymbolAddress((void**)&acc1, g_acc1);
    cudaGetSymbolAddress((void**)&acc2, g_acc2);

    const int SM64 = 10 * 64 * 32 * 4;  // 81920 B
    const int SM32 = 10 * 32 * 32 * 4;  // 40960 B
    cudaFuncSetAttribute(node_gemm<64, 0>,
                         cudaFuncAttributeMaxDynamicSharedMemorySize, SM64);
    cudaFuncSetAttribute(node_gemm<64, 1>,
                         cudaFuncAttributeMaxDynamicSharedMemorySize, SM64);
    cudaFuncSetAttribute(node_gemm<32, 2>,
                         cudaFuncAttributeMaxDynamicSharedMemorySize, SM32);

    const int G = 296;       // 2 blocks/SM
    int eb = (E + 31) / 32;  // 4 edges/warp, 8 warps/block
    int nb4 = (Nn * 32 / 4 + 255) / 256;
    float* out = (float*)d_out;

    // ---- layer 1: x -> Zh, acc1(root) ; edge -> acc1
    node_gemm<64, 0><<<G, 256, SM64>>>(x, nullptr, W1, root1, b1, Zh, acc1,
                                       Nn, G * 8);
    edge_kernel<<<eb, 256>>>(Zh, ei, pseudo, acc1, E);

    // ---- layer 2: [relu(acc1)||skip] -> Zh, acc2(root) ; edge -> acc2
    node_gemm<64, 1><<<G, 256, SM64>>>(acc1, skip, W1, root1, b1, Zh, acc2,
                                       Nn, G * 8);
    edge_kernel<<<eb, 256>>>(Zh, ei, pseudo, acc2, E);

    // ---- layer 3: relu(acc2) -> Zh, out(root) ; edge -> out ; relu
    node_gemm<32, 2><<<G, 256, SM32>>>(acc2, nullptr, W2, root2, b2, Zh, out,
                                       Nn, G * 8);
    edge_kernel<<<eb, 256>>>(Zh, ei, pseudo, out, E);
    relu4_kernel<<<nb4, 256>>>((float4*)out, Nn * 32 / 4);
}

// round 8
// speedup vs baseline: 6.9733x; 1.0412x over previous
#include <cuda_runtime.h>
#include <cuda_fp16.h>

// ---------------------------------------------------------------------------
// MeshUpConv via node-domain weight transform:
//   Z[n, k*32+o] = (X @ W[k])[n,o]  stored fp16 (gather traffic halved);
//   slot 9 = root -> acc (+bias), fp32.
//   edge: acc[dst, o] += sum_k B[e,k] * Z[src, k*32+o]   (fp32 accumulate)
// Node GEMM: 6 nodes/warp (no reg spill), f32x2 FMA, W in smem.
// Edge: 4 lanes/edge, LDG.128 fp16, vectorized REDG.
// edge_index arrives as int32 (JAX x64 disabled).
// ---------------------------------------------------------------------------

#define NMAX 50000
#define EMAX 400000

__device__ __half g_Zh[NMAX * 288];   // 28.8 MB, L2-resident
__device__ float g_acc1[NMAX * 32];
__device__ float g_acc2[NMAX * 32];

// ---- packed f32x2 helpers (sm_103a) ---------------------------------------
__device__ __forceinline__ unsigned long long pack2(float x) {
    unsigned long long r;
    asm("mov.b64 %0, {%1,%1};" : "=l"(r) : "f"(x));
    return r;
}
__device__ __forceinline__ void fma2(unsigned long long& d,
                                     unsigned long long a,
                                     unsigned long long b) {
    asm("fma.rn.f32x2 %0, %1, %2, %0;" : "+l"(d) : "l"(a), "l"(b));
}
__device__ __forceinline__ float2 unpack2(unsigned long long v) {
    float2 f;
    asm("mov.b64 {%0,%1}, %2;" : "=f"(f.x), "=f"(f.y) : "l"(v));
    return f;
}
__device__ __forceinline__ void red_add_v4(float* addr, float a, float b,
                                           float c, float d) {
    asm volatile("red.global.add.v4.f32 [%0], {%1,%2,%3,%4};"
                 :: "l"(addr), "f"(a), "f"(b), "f"(c), "f"(d)
                 : "memory");
}

// ---- node GEMM, 6 nodes per warp (NT=6, no spill) --------------------------
// MODE 0: X plain [N,CIN];  MODE 1: [relu(A)||S] (CIN=64);  MODE 2: relu(A) (CIN=32)
#define NT 6
template <int CIN, int MODE>
__global__ void __launch_bounds__(256, 2) node_gemm(
    const float* __restrict__ Xa, const float* __restrict__ Xb,
    const float* __restrict__ W, const float* __restrict__ root,
    const float* __restrict__ bias, __half* __restrict__ Zh,
    float* __restrict__ acc, int Nn, int nwarps) {
    extern __shared__ float Wsm[];  // [10][CIN][32]: 0-8 = W, 9 = root
    __shared__ float bsm[32];
    const int WT = 9 * CIN * 32;
    for (int i = threadIdx.x; i < WT; i += 256) Wsm[i] = W[i];
    for (int i = threadIdx.x; i < CIN * 32; i += 256) Wsm[WT + i] = root[i];
    if (threadIdx.x < 32) bsm[threadIdx.x] = bias[threadIdx.x];
    __syncthreads();

    const unsigned long long* Wsm2 =
        reinterpret_cast<const unsigned long long*>(Wsm);
    int lane = threadIdx.x & 31;
    int gw = (blockIdx.x * 256 + threadIdx.x) >> 5;

    for (int n0 = gw * NT; n0 < Nn; n0 += nwarps * NT) {
        float xlo[NT], xhi[NT];
#pragma unroll
        for (int j = 0; j < NT; j++) {
            int n = n0 + j;
            bool v = (n < Nn);
            if (MODE == 0) {
                xlo[j] = v ? Xa[(long long)n * CIN + lane] : 0.f;
                xhi[j] = (CIN == 64 && v) ? Xa[(long long)n * CIN + 32 + lane] : 0.f;
            } else if (MODE == 1) {
                xlo[j] = v ? fmaxf(Xa[n * 32 + lane], 0.f) : 0.f;
                xhi[j] = v ? Xb[n * 32 + lane] : 0.f;
            } else {
                xlo[j] = v ? fmaxf(Xa[n * 32 + lane], 0.f) : 0.f;
                xhi[j] = 0.f;
            }
        }

        unsigned long long au[NT][5];
#pragma unroll
        for (int j = 0; j < NT; j++)
#pragma unroll
            for (int i = 0; i < 5; i++) au[j][i] = 0ULL;

#pragma unroll
        for (int c = 0; c < CIN; c++) {
            unsigned long long w[5];
#pragma unroll
            for (int i = 0; i < 5; i++) {
                int P = lane + 32 * i;  // pair id 0..159
                w[i] = Wsm2[(P >> 4) * (CIN * 16) + c * 16 + (P & 15)];
            }
#pragma unroll
            for (int j = 0; j < NT; j++) {
                float xc =
                    __shfl_sync(0xffffffffu, (c < 32) ? xlo[j] : xhi[j], c & 31);
                unsigned long long xp = pack2(xc);
#pragma unroll
                for (int i = 0; i < 5; i++) fma2(au[j][i], w[i], xp);
            }
        }

#pragma unroll
        for (int j = 0; j < NT; j++) {
            int n = n0 + j;
            if (n >= Nn) break;
#pragma unroll
            for (int i = 0; i < 5; i++) {
                int P = lane + 32 * i;
                int slot = P >> 4, pr = P & 15;
                float2 f = unpack2(au[j][i]);
                if (slot < 9) {
                    *reinterpret_cast<__half2*>(&Zh[(long long)n * 288 + 2 * P]) =
                        __floats2half2_rn(f.x, f.y);
                } else {
                    acc[n * 32 + 2 * pr + 0] = f.x + bsm[2 * pr + 0];
                    acc[n * 32 + 2 * pr + 1] = f.y + bsm[2 * pr + 1];
                }
            }
        }
    }
}

// ---- edge phase: 4 lanes/edge, 8 fp16 channels/lane, fp32 accumulate -------
__global__ void __launch_bounds__(256) edge_kernel(
    const __half* __restrict__ Zh, const int* __restrict__ ei,
    const float* __restrict__ pseudo, float* __restrict__ acc, int E) {
    int warp = (blockIdx.x * 256 + threadIdx.x) >> 5;
    int lane = threadIdx.x & 31;
    int sub = lane >> 2;   // edge within warp (0..7)
    int li = lane & 3;     // 8-half channel group (0..3)
    int e = warp * 8 + sub;
    if (e >= E) return;

    int s = __ldg(ei + e);
    int d = __ldg(ei + E + e);
    float2 ps = __ldg(reinterpret_cast<const float2*>(pseudo) + e);
    float t0 = ps.x, t1 = ps.y;

    float q0[3], q1[3];
    q0[0] = 0.5f * (1.f - t0) * (1.f - t0);
    q0[1] = -t0 * t0 + t0 + 0.5f;
    q0[2] = 0.5f * t0 * t0;
    q1[0] = 0.5f * (1.f - t1) * (1.f - t1);
    q1[1] = -t1 * t1 + t1 + 0.5f;
    q1[2] = 0.5f * t1 * t1;

    // lane reads 8 halves (16B) per slot at half-offset k*32 + li*8
    const uint4* zs =
        reinterpret_cast<const uint4*>(Zh + (long long)s * 288) + li;
    float a[8];
#pragma unroll
    for (int i = 0; i < 8; i++) a[i] = 0.f;

#pragma unroll
    for (int k1 = 0; k1 < 3; k1++) {
#pragma unroll
        for (int k0 = 0; k0 < 3; k0++) {
            float bk = q1[k1] * q0[k0];
            uint4 z = __ldg(zs + (k1 * 3 + k0) * 4);
            float2 f0 = __half22float2(*reinterpret_cast<__half2*>(&z.x));
            float2 f1 = __half22float2(*reinterpret_cast<__half2*>(&z.y));
            float2 f2 = __half22float2(*reinterpret_cast<__half2*>(&z.z));
            float2 f3 = __half22float2(*reinterpret_cast<__half2*>(&z.w));
            a[0] = fmaf(bk, f0.x, a[0]);
            a[1] = fmaf(bk, f0.y, a[1]);
            a[2] = fmaf(bk, f1.x, a[2]);
            a[3] = fmaf(bk, f1.y, a[3]);
            a[4] = fmaf(bk, f2.x, a[4]);
            a[5] = fmaf(bk, f2.y, a[5]);
            a[6] = fmaf(bk, f3.x, a[6]);
            a[7] = fmaf(bk, f3.y, a[7]);
        }
    }

    float* dp = acc + (long long)d * 32 + li * 8;
    red_add_v4(dp + 0, a[0], a[1], a[2], a[3]);
    red_add_v4(dp + 4, a[4], a[5], a[6], a[7]);
}

__global__ void relu4_kernel(float4* __restrict__ a, int total4) {
    int i = blockIdx.x * blockDim.x + threadIdx.x;
    if (i < total4) {
        float4 v = a[i];
        v.x = fmaxf(v.x, 0.f); v.y = fmaxf(v.y, 0.f);
        v.z = fmaxf(v.z, 0.f); v.w = fmaxf(v.w, 0.f);
        a[i] = v;
    }
}

// ---------------------------------------------------------------------------
extern "C" void kernel_launch(void* const* d_in, const int* in_sizes, int n_in,
                              void* d_out, int out_size) {
    const float* x = (const float*)d_in[0];      // [N,64]
    const int* ei = (const int*)d_in[1];         // [2,E] int32
    const float* pseudo = (const float*)d_in[2]; // [E,2]
    const float* skip = (const float*)d_in[3];   // [N,32]
    const float* W1 = (const float*)d_in[4];     // [9,64,32]
    const float* root1 = (const float*)d_in[5];  // [64,32]
    const float* b1 = (const float*)d_in[6];     // [32]
    const float* W2 = (const float*)d_in[7];     // [9,32,32]
    const float* root2 = (const float*)d_in[8];  // [32,32]
    const float* b2 = (const float*)d_in[9];     // [32]

    int Nn = in_sizes[0] / 64;
    int E = in_sizes[1] / 2;

    __half* Zh;
    float *acc1, *acc2;
    cudaGetSymbolAddress((void**)&Zh, g_Zh);
    cudaGetSymbolAddress((void**)&acc1, g_acc1);
    cudaGetSymbolAddress((void**)&acc2, g_acc2);

    const int SM64 = 10 * 64 * 32 * 4;  // 81920 B
    const int SM32 = 10 * 32 * 32 * 4;  // 40960 B
    cudaFuncSetAttribute(node_gemm<64, 0>,
                         cudaFuncAttributeMaxDynamicSharedMemorySize, SM64);
    cudaFuncSetAttribute(node_gemm<64, 1>,
                         cudaFuncAttributeMaxDynamicSharedMemorySize, SM64);
    cudaFuncSetAttribute(node_gemm<32, 2>,
                         cudaFuncAttributeMaxDynamicSharedMemorySize, SM32);

    const int G = 296;       // 2 blocks/SM
    int eb = (E + 63) / 64;  // 8 edges/warp, 8 warps/block
    int nb4 = (Nn * 32 / 4 + 255) / 256;
    float* out = (float*)d_out;

    // ---- layer 1: x -> Zh, acc1(root) ; edge -> acc1
    node_gemm<64, 0><<<G, 256, SM64>>>(x, nullptr, W1, root1, b1, Zh, acc1,
                                       Nn, G * 8);
    edge_kernel<<<eb, 256>>>(Zh, ei, pseudo, acc1, E);

    // ---- layer 2: [relu(acc1)||skip] -> Zh, acc2(root) ; edge -> acc2
    node_gemm<64, 1><<<G, 256, SM64>>>(acc1, skip, W1, root1, b1, Zh, acc2,
                                       Nn, G * 8);
    edge_kernel<<<eb, 256>>>(Zh, ei, pseudo, acc2, E);

    // ---- layer 3: relu(acc2) -> Zh, out(root) ; edge -> out ; relu
    node_gemm<32, 2><<<G, 256, SM32>>>(acc2, nullptr, W2, root2, b2, Zh, out,
                                       Nn, G * 8);
    edge_kernel<<<eb, 256>>>(Zh, ei, pseudo, out, E);
    relu4_kernel<<<nb4, 256>>>((float4*)out, Nn * 32 / 4);
}